// round 5
// baseline (speedup 1.0000x reference)
#include <cuda_runtime.h>
#include <math.h>

#define B_CONSTF 0.9f
#define EPSF 1e-10f
#define SCALEF 0.0625f

typedef unsigned long long ull;

// ---------------- device scratch ----------------
__device__ float g_qh[16*512*32];    // per-head Q   [bh][s][32]
__device__ float g_kh[16*512*32];    // per-head K   [bh][s][32]
__device__ float g_v [1024*256];     // V row-major  [b*s][256]
__device__ float g_vz[16*512*32];    // v_norm^p     [bh][s][32]
__device__ float g_s [16*512*512];   // exp scores   [bh][q][k]  (16.8MB)
__device__ float g_lp[16*8*512];     // row-sum partials [bh][ktile][q]
__device__ float g_e [1024*256];     // power-mean result (row-major)
__device__ float g_vmin[512], g_nscale[512], g_unscale[512];
__device__ float g_p[256], g_invp[256];

// ---------------- f32x2 helpers ----------------
__device__ __forceinline__ ull f2pack(float lo, float hi) {
    ull r; asm("mov.b64 %0, {%1, %2};" : "=l"(r) : "f"(lo), "f"(hi)); return r;
}
__device__ __forceinline__ void f2unpack(ull v, float& lo, float& hi) {
    asm("mov.b64 {%0, %1}, %2;" : "=f"(lo), "=f"(hi) : "l"(v));
}
__device__ __forceinline__ ull f2fma(ull a, ull b, ull c) {
    ull d; asm("fma.rn.f32x2 %0, %1, %2, %3;" : "=l"(d) : "l"(a), "l"(b), "l"(c)); return d;
}

// =========================================================================
// Kernel 1: fused QKV projection.  C[1024][768] = ctx @ [W_Q; W_KV]^T
// 64x64 tiles, 128 thr, micro 8m x 4n (m as 4 f32x2 pairs). BK=16.
// =========================================================================
__global__ __launch_bounds__(128) void qkv_gemm(
    const float* __restrict__ ctx, const float* __restrict__ W_Q,
    const float* __restrict__ W_KV)
{
    __shared__ float As[16][68];
    __shared__ float Bs[16][68];
    const int tid = threadIdx.x;
    const int tx = tid & 15, ty = tid >> 4;   // ty 0..7
    const int bm = blockIdx.y * 64;
    const int bn = blockIdx.x * 64;
    const float* Bsrc = (bn < 256) ? (W_Q + (size_t)bn * 256)
                                   : (W_KV + (size_t)(bn - 256) * 256);
    const int lm = tid & 63, lh = tid >> 6;   // fill: row lm, k-half lh

    ull acc[4][4];
    #pragma unroll
    for (int n = 0; n < 4; n++)
        #pragma unroll
        for (int i = 0; i < 4; i++) acc[n][i] = 0ULL;

    for (int k0 = 0; k0 < 256; k0 += 16) {
        #pragma unroll
        for (int r = 0; r < 2; r++) {
            int c = lh*8 + r*4;
            float4 a4 = *(const float4*)&ctx [(size_t)(bm + lm)*256 + k0 + c];
            As[c+0][lm] = a4.x; As[c+1][lm] = a4.y;
            As[c+2][lm] = a4.z; As[c+3][lm] = a4.w;
            float4 b4 = *(const float4*)&Bsrc[(size_t)lm*256 + k0 + c];
            Bs[c+0][lm] = b4.x; Bs[c+1][lm] = b4.y;
            Bs[c+2][lm] = b4.z; Bs[c+3][lm] = b4.w;
        }
        __syncthreads();
        #pragma unroll
        for (int kk = 0; kk < 16; kk++) {
            ulonglong2 A0 = *(const ulonglong2*)&As[kk][ty*8];
            ulonglong2 A1 = *(const ulonglong2*)&As[kk][ty*8 + 4];
            ull a0 = A0.x, a1 = A0.y, a2 = A1.x, a3 = A1.y;
            float4 bf = *(const float4*)&Bs[kk][tx*4];
            ull b0 = f2pack(bf.x, bf.x), b1 = f2pack(bf.y, bf.y);
            ull b2 = f2pack(bf.z, bf.z), b3 = f2pack(bf.w, bf.w);
            acc[0][0]=f2fma(b0,a0,acc[0][0]); acc[0][1]=f2fma(b0,a1,acc[0][1]);
            acc[0][2]=f2fma(b0,a2,acc[0][2]); acc[0][3]=f2fma(b0,a3,acc[0][3]);
            acc[1][0]=f2fma(b1,a0,acc[1][0]); acc[1][1]=f2fma(b1,a1,acc[1][1]);
            acc[1][2]=f2fma(b1,a2,acc[1][2]); acc[1][3]=f2fma(b1,a3,acc[1][3]);
            acc[2][0]=f2fma(b2,a0,acc[2][0]); acc[2][1]=f2fma(b2,a1,acc[2][1]);
            acc[2][2]=f2fma(b2,a2,acc[2][2]); acc[2][3]=f2fma(b2,a3,acc[2][3]);
            acc[3][0]=f2fma(b3,a0,acc[3][0]); acc[3][1]=f2fma(b3,a1,acc[3][1]);
            acc[3][2]=f2fma(b3,a2,acc[3][2]); acc[3][3]=f2fma(b3,a3,acc[3][3]);
        }
        __syncthreads();
    }

    float v[4][8];
    #pragma unroll
    for (int n = 0; n < 4; n++)
        #pragma unroll
        for (int i = 0; i < 4; i++)
            f2unpack(acc[n][i], v[n][2*i], v[n][2*i+1]);
    const int c = bn + tx*4;
    #pragma unroll
    for (int r = 0; r < 8; r++) {
        int row = bm + ty*8 + r;
        float4 o = make_float4(v[0][r], v[1][r], v[2][r], v[3][r]);
        int b = row >> 9, s = row & 511;
        if (c < 256) {
            int h = c >> 5, a = c & 31;
            *(float4*)&g_qh[((size_t)((b*8+h)*512 + s))*32 + a] = o;
        } else if (c < 512) {
            int kc = c - 256, h = kc >> 5, a = kc & 31;
            *(float4*)&g_kh[((size_t)((b*8+h)*512 + s))*32 + a] = o;
        } else {
            *(float4*)&g_v[(size_t)row * 256 + (c - 512)] = o;
        }
    }
}

// =========================================================================
// Kernel 2: v min/max per (b,d) + p/invp.  grid (8 dchunk, 2 b), 256 thr.
// =========================================================================
__global__ __launch_bounds__(256) void vstats_kernel(const float* __restrict__ p_param) {
    __shared__ float smn[8][32], smx[8][32];
    const int b = blockIdx.y, dc = blockIdx.x;
    const int dd = threadIdx.x & 31, sl = threadIdx.x >> 5;
    const int d = dc*32 + dd;
    float mn = 1e30f, mx = -1e30f;
    const float* base = g_v + (size_t)(b*512 + sl*64) * 256 + d;
    #pragma unroll 4
    for (int i = 0; i < 64; i++) {
        float v = base[(size_t)i * 256];
        mn = fminf(mn, v); mx = fmaxf(mx, v);
    }
    smn[sl][dd] = mn; smx[sl][dd] = mx;
    __syncthreads();
    if (sl == 0) {
        #pragma unroll
        for (int t = 1; t < 8; t++) {
            mn = fminf(mn, smn[t][dd]); mx = fmaxf(mx, smx[t][dd]);
        }
        float range = mx - mn + EPSF;
        g_vmin   [b*256 + d] = mn;
        g_nscale [b*256 + d] = (1.0f - B_CONSTF) / range;
        g_unscale[b*256 + d] = range / (1.0f - B_CONSTF);
        if (b == 0) {
            float pp = p_param[d];
            float p  = 50000.0f * tanhf(0.005f * pp) + 1.0f;
            if (p == 0.0f) p = 1e-4f;
            g_p[d] = p; g_invp[d] = 1.0f / p;
        }
    }
}

// =========================================================================
// Kernel 3: vz = v_norm^p per-head.  grid (8 schunk, 16 bh), 256 thr.
// =========================================================================
__global__ __launch_bounds__(256) void vz_kernel() {
    __shared__ float s_p[32], s_ns[32], s_vm[32];
    const int bh = blockIdx.y, sc = blockIdx.x;
    const int b = bh >> 3, h = bh & 7;
    const int tid = threadIdx.x;
    if (tid < 32) {
        int d = h*32 + tid;
        s_p[tid]  = g_p[d];
        s_ns[tid] = g_nscale[b*256 + d];
        s_vm[tid] = g_vmin[b*256 + d];
    }
    __syncthreads();
    const int a = tid & 31, sq = tid >> 5;
    #pragma unroll
    for (int it = 0; it < 8; it++) {
        int s = sc*64 + it*8 + sq;
        float v  = g_v[(size_t)(b*512 + s) * 256 + h*32 + a];
        float vn = (v - s_vm[a]) * s_ns[a] + B_CONSTF;
        g_vz[((size_t)(bh*512 + s))*32 + a] = __expf(s_p[a] * __logf(vn));
    }
}

// =========================================================================
// Kernel 4: pass1 scores.  S[bh] = exp(Q@K^T * scale), + row-sum partials.
// grid (8 kt, 8 qt, 16 bh), 128 thr, 64x64 tile, micro 8m x 4n, K=32.
// =========================================================================
__global__ __launch_bounds__(128) void pass1_kernel() {
    __shared__ float As[32][68];
    __shared__ float Bs[32][68];
    const int kt = blockIdx.x, qt = blockIdx.y, bh = blockIdx.z;
    const int tid = threadIdx.x, tx = tid & 15, ty = tid >> 4;
    const float* Aq = g_qh + (size_t)bh*512*32 + (size_t)qt*64*32;
    const float* Bk = g_kh + (size_t)bh*512*32 + (size_t)kt*64*32;
    const int lm = tid & 63, lh = tid >> 6;
    #pragma unroll
    for (int r = 0; r < 4; r++) {
        int c = lh*16 + r*4;
        float4 a4 = *(const float4*)&Aq[lm*32 + c];
        As[c+0][lm] = a4.x; As[c+1][lm] = a4.y;
        As[c+2][lm] = a4.z; As[c+3][lm] = a4.w;
        float4 b4 = *(const float4*)&Bk[lm*32 + c];
        Bs[c+0][lm] = b4.x; Bs[c+1][lm] = b4.y;
        Bs[c+2][lm] = b4.z; Bs[c+3][lm] = b4.w;
    }
    __syncthreads();

    ull acc[4][4];
    #pragma unroll
    for (int n = 0; n < 4; n++)
        #pragma unroll
        for (int i = 0; i < 4; i++) acc[n][i] = 0ULL;
    #pragma unroll
    for (int kk = 0; kk < 32; kk++) {
        ulonglong2 A0 = *(const ulonglong2*)&As[kk][ty*8];
        ulonglong2 A1 = *(const ulonglong2*)&As[kk][ty*8 + 4];
        ull a0 = A0.x, a1 = A0.y, a2 = A1.x, a3 = A1.y;
        float4 bf = *(const float4*)&Bs[kk][tx*4];
        ull b0 = f2pack(bf.x, bf.x), b1 = f2pack(bf.y, bf.y);
        ull b2 = f2pack(bf.z, bf.z), b3 = f2pack(bf.w, bf.w);
        acc[0][0]=f2fma(b0,a0,acc[0][0]); acc[0][1]=f2fma(b0,a1,acc[0][1]);
        acc[0][2]=f2fma(b0,a2,acc[0][2]); acc[0][3]=f2fma(b0,a3,acc[0][3]);
        acc[1][0]=f2fma(b1,a0,acc[1][0]); acc[1][1]=f2fma(b1,a1,acc[1][1]);
        acc[1][2]=f2fma(b1,a2,acc[1][2]); acc[1][3]=f2fma(b1,a3,acc[1][3]);
        acc[2][0]=f2fma(b2,a0,acc[2][0]); acc[2][1]=f2fma(b2,a1,acc[2][1]);
        acc[2][2]=f2fma(b2,a2,acc[2][2]); acc[2][3]=f2fma(b2,a3,acc[2][3]);
        acc[3][0]=f2fma(b3,a0,acc[3][0]); acc[3][1]=f2fma(b3,a1,acc[3][1]);
        acc[3][2]=f2fma(b3,a2,acc[3][2]); acc[3][3]=f2fma(b3,a3,acc[3][3]);
    }

    float w[4][8];
    #pragma unroll
    for (int n = 0; n < 4; n++)
        #pragma unroll
        for (int i = 0; i < 4; i++)
            f2unpack(acc[n][i], w[n][2*i], w[n][2*i+1]);
    float rs[8];
    #pragma unroll
    for (int r = 0; r < 8; r++) rs[r] = 0.f;
    #pragma unroll
    for (int n = 0; n < 4; n++)
        #pragma unroll
        for (int r = 0; r < 8; r++) {
            w[n][r] = __expf(w[n][r] * SCALEF);
            rs[r] += w[n][r];
        }
    float* Sout = g_s + (size_t)bh*512*512;
    #pragma unroll
    for (int r = 0; r < 8; r++) {
        int row = qt*64 + ty*8 + r;
        float4 o = make_float4(w[0][r], w[1][r], w[2][r], w[3][r]);
        *(float4*)&Sout[(size_t)row*512 + kt*64 + tx*4] = o;
    }
    #pragma unroll
    for (int r = 0; r < 8; r++) {
        rs[r] += __shfl_xor_sync(0xffffffffu, rs[r], 1);
        rs[r] += __shfl_xor_sync(0xffffffffu, rs[r], 2);
        rs[r] += __shfl_xor_sync(0xffffffffu, rs[r], 4);
        rs[r] += __shfl_xor_sync(0xffffffffu, rs[r], 8);
    }
    if ((tid & 15) == 0) {
        #pragma unroll
        for (int r = 0; r < 8; r++)
            g_lp[((size_t)(bh*8 + kt))*512 + qt*64 + ty*8 + r] = rs[r];
    }
}

// =========================================================================
// Kernel 5: pass2 + merged power-mean epilogue.
// g_e rows = ((S @ Vz)/L)^(1/p) unscaled.  Full K=512 (no split-K).
// grid (8 mt, 16 bh), 128 thr, 64m x 32n tile, micro 8m x 2n, BK=16.
// =========================================================================
__global__ __launch_bounds__(128) void pass2_kernel() {
    __shared__ float As[16][68];
    __shared__ float Bs[16][36];
    __shared__ float sinvL[64];
    const int mt = blockIdx.x, bh = blockIdx.y;
    const int b = bh >> 3, h = bh & 7;
    const int tid = threadIdx.x, tx = tid & 15, ty = tid >> 4;
    const float* Ab = g_s  + (size_t)bh*512*512 + (size_t)mt*64*512;
    const float* Bb = g_vz + (size_t)bh*512*32;
    const int lm = tid & 63, lh = tid >> 6;
    const int bkr = tid >> 3, bcl = (tid & 7) * 4;

    if (tid < 64) {
        int q = mt*64 + tid;
        float L = 0.f;
        #pragma unroll
        for (int kt = 0; kt < 8; kt++) L += g_lp[((size_t)(bh*8 + kt))*512 + q];
        sinvL[tid] = 1.0f / L;
    }

    ull acc[2][4];
    #pragma unroll
    for (int n = 0; n < 2; n++)
        #pragma unroll
        for (int i = 0; i < 4; i++) acc[n][i] = 0ULL;

    for (int k0 = 0; k0 < 512; k0 += 16) {
        #pragma unroll
        for (int r = 0; r < 2; r++) {
            int c = lh*8 + r*4;
            float4 a4 = *(const float4*)&Ab[(size_t)lm*512 + k0 + c];
            As[c+0][lm] = a4.x; As[c+1][lm] = a4.y;
            As[c+2][lm] = a4.z; As[c+3][lm] = a4.w;
        }
        float4 b4 = *(const float4*)&Bb[(size_t)(k0 + bkr)*32 + bcl];
        *(float4*)&Bs[bkr][bcl] = b4;
        __syncthreads();
        #pragma unroll
        for (int kk = 0; kk < 16; kk++) {
            ulonglong2 A0 = *(const ulonglong2*)&As[kk][ty*8];
            ulonglong2 A1 = *(const ulonglong2*)&As[kk][ty*8 + 4];
            ull a0 = A0.x, a1 = A0.y, a2 = A1.x, a3 = A1.y;
            float2 bf = *(const float2*)&Bs[kk][tx*2];
            ull b0 = f2pack(bf.x, bf.x), b1 = f2pack(bf.y, bf.y);
            acc[0][0]=f2fma(b0,a0,acc[0][0]); acc[0][1]=f2fma(b0,a1,acc[0][1]);
            acc[0][2]=f2fma(b0,a2,acc[0][2]); acc[0][3]=f2fma(b0,a3,acc[0][3]);
            acc[1][0]=f2fma(b1,a0,acc[1][0]); acc[1][1]=f2fma(b1,a1,acc[1][1]);
            acc[1][2]=f2fma(b1,a2,acc[1][2]); acc[1][3]=f2fma(b1,a3,acc[1][3]);
        }
        __syncthreads();
    }

    float v[2][8];
    #pragma unroll
    for (int n = 0; n < 2; n++)
        #pragma unroll
        for (int i = 0; i < 4; i++)
            f2unpack(acc[n][i], v[n][2*i], v[n][2*i+1]);

    const int a0 = h*32 + tx*2;
    const float ip0 = g_invp[a0],            ip1 = g_invp[a0+1];
    const float us0 = g_unscale[b*256 + a0], us1 = g_unscale[b*256 + a0 + 1];
    const float vm0 = g_vmin[b*256 + a0],    vm1 = g_vmin[b*256 + a0 + 1];
    #pragma unroll
    for (int r = 0; r < 8; r++) {
        int q = mt*64 + ty*8 + r;
        float il = sinvL[ty*8 + r];
        float e0 = __expf(__logf(v[0][r] * il) * ip0);
        float e1 = __expf(__logf(v[1][r] * il) * ip1);
        float2 o = make_float2((e0 - B_CONSTF) * us0 + vm0,
                               (e1 - B_CONSTF) * us1 + vm1);
        *(float2*)&g_e[(size_t)(b*512 + q)*256 + a0] = o;
    }
}

// =========================================================================
// Kernel 6: output projection.  out[1024][256] = g_e @ W_out^T.
// grid (8 nt(32), 16 mt(64)), 128 thr, micro 8m x 2n, BK=16.
// =========================================================================
__global__ __launch_bounds__(128) void out_gemm(const float* __restrict__ Wo,
                                                float* __restrict__ out) {
    __shared__ float As[16][68];
    __shared__ float Bs[16][36];
    const int bn = blockIdx.x * 32;
    const int bm = blockIdx.y * 64;
    const int tid = threadIdx.x, tx = tid & 15, ty = tid >> 4;
    const int lm = tid & 63, lh = tid >> 6;
    const int ln = tid & 31, lk = tid >> 5;   // B fill: row ln, col-group lk

    ull acc[2][4];
    #pragma unroll
    for (int n = 0; n < 2; n++)
        #pragma unroll
        for (int i = 0; i < 4; i++) acc[n][i] = 0ULL;

    for (int k0 = 0; k0 < 256; k0 += 16) {
        #pragma unroll
        for (int r = 0; r < 2; r++) {
            int c = lh*8 + r*4;
            float4 a4 = *(const float4*)&g_e[(size_t)(bm + lm)*256 + k0 + c];
            As[c+0][lm] = a4.x; As[c+1][lm] = a4.y;
            As[c+2][lm] = a4.z; As[c+3][lm] = a4.w;
        }
        float4 w4 = *(const float4*)&Wo[(size_t)(bn + ln)*256 + k0 + lk*4];
        Bs[lk*4+0][ln] = w4.x; Bs[lk*4+1][ln] = w4.y;
        Bs[lk*4+2][ln] = w4.z; Bs[lk*4+3][ln] = w4.w;
        __syncthreads();
        #pragma unroll
        for (int kk = 0; kk < 16; kk++) {
            ulonglong2 A0 = *(const ulonglong2*)&As[kk][ty*8];
            ulonglong2 A1 = *(const ulonglong2*)&As[kk][ty*8 + 4];
            ull a0 = A0.x, a1 = A0.y, a2 = A1.x, a3 = A1.y;
            float2 bf = *(const float2*)&Bs[kk][tx*2];
            ull b0 = f2pack(bf.x, bf.x), b1 = f2pack(bf.y, bf.y);
            acc[0][0]=f2fma(b0,a0,acc[0][0]); acc[0][1]=f2fma(b0,a1,acc[0][1]);
            acc[0][2]=f2fma(b0,a2,acc[0][2]); acc[0][3]=f2fma(b0,a3,acc[0][3]);
            acc[1][0]=f2fma(b1,a0,acc[1][0]); acc[1][1]=f2fma(b1,a1,acc[1][1]);
            acc[1][2]=f2fma(b1,a2,acc[1][2]); acc[1][3]=f2fma(b1,a3,acc[1][3]);
        }
        __syncthreads();
    }
    float v[2][8];
    #pragma unroll
    for (int n = 0; n < 2; n++)
        #pragma unroll
        for (int i = 0; i < 4; i++)
            f2unpack(acc[n][i], v[n][2*i], v[n][2*i+1]);
    #pragma unroll
    for (int r = 0; r < 8; r++) {
        float2 o = make_float2(v[0][r], v[1][r]);
        *(float2*)&out[(size_t)(bm + ty*8 + r)*256 + bn + tx*2] = o;
    }
}

// ---------------- launch ----------------
extern "C" void kernel_launch(void* const* d_in, const int* in_sizes, int n_in,
                              void* d_out, int out_size) {
    const float* context = (const float*)d_in[0];
    const float* W_Q     = (const float*)d_in[1];
    const float* W_KV    = (const float*)d_in[2];
    const float* W_out   = (const float*)d_in[3];
    const float* p_param = (const float*)d_in[4];
    float* out = (float*)d_out;

    qkv_gemm    <<<dim3(12, 16),    128>>>(context, W_Q, W_KV);
    vstats_kernel<<<dim3(8, 2),     256>>>(p_param);
    vz_kernel   <<<dim3(8, 16),     256>>>();
    pass1_kernel<<<dim3(8, 8, 16),  128>>>();
    pass2_kernel<<<dim3(8, 16),     128>>>();
    out_gemm    <<<dim3(8, 16),     128>>>(W_out, out);
}

// round 7
// speedup vs baseline: 1.0937x; 1.0937x over previous
#include <cuda_runtime.h>
#include <math.h>

#define B_CONSTF 0.9f
#define EPSF 1e-10f
#define SCALEF 0.0625f

typedef unsigned long long ull;

// ---------------- device scratch ----------------
__device__ float g_qh[16*512*32];    // per-head Q   [bh][s][32]
__device__ float g_kh[16*512*32];    // per-head K   [bh][s][32]
__device__ float g_v [1024*256];     // V row-major  [b*s][256]
__device__ float g_vz[16*512*32];    // v_norm^p     [bh][s][32]
__device__ float g_s [16*512*512];   // exp scores   [bh][q][k]  (16.8MB)
__device__ float g_lp[16*8*512];     // row-sum partials [bh][ktile][q]
__device__ float g_e [1024*256];     // power-mean result (row-major)
__device__ float g_vmin[512], g_nscale[512], g_unscale[512];
__device__ float g_p[256], g_invp[256];

// ---------------- f32x2 helpers ----------------
__device__ __forceinline__ ull f2pack(float lo, float hi) {
    ull r; asm("mov.b64 %0, {%1, %2};" : "=l"(r) : "f"(lo), "f"(hi)); return r;
}
__device__ __forceinline__ void f2unpack(ull v, float& lo, float& hi) {
    asm("mov.b64 {%0, %1}, %2;" : "=f"(lo), "=f"(hi) : "l"(v));
}
__device__ __forceinline__ ull f2fma(ull a, ull b, ull c) {
    ull d; asm("fma.rn.f32x2 %0, %1, %2, %3;" : "=l"(d) : "l"(a), "l"(b), "l"(c)); return d;
}

// =========================================================================
// Kernel 1: fused QKV projection (round-4 proven form).
// C[1024][768] = ctx @ [W_Q; W_KV]^T.  64x64 tiles, 256 thr, micro 4m x 4n.
// =========================================================================
__global__ __launch_bounds__(256) void qkv_gemm(
    const float* __restrict__ ctx, const float* __restrict__ W_Q,
    const float* __restrict__ W_KV)
{
    __shared__ float As[16][68];
    __shared__ float Bs[16][68];
    const int tid = threadIdx.x;
    const int tx = tid & 15, ty = tid >> 4;
    const int bm = blockIdx.y * 64;
    const int bn = blockIdx.x * 64;
    const float* Bsrc = (bn < 256) ? (W_Q + (size_t)bn * 256)
                                   : (W_KV + (size_t)(bn - 256) * 256);
    const int lm = tid >> 2, lc = tid & 3;

    ull acc[4][2];
    #pragma unroll
    for (int n = 0; n < 4; n++) { acc[n][0] = 0ULL; acc[n][1] = 0ULL; }

    for (int k0 = 0; k0 < 256; k0 += 16) {
        float4 a4 = *(const float4*)&ctx [(size_t)(bm + lm) * 256 + k0 + lc*4];
        As[lc*4+0][lm] = a4.x; As[lc*4+1][lm] = a4.y;
        As[lc*4+2][lm] = a4.z; As[lc*4+3][lm] = a4.w;
        float4 b4 = *(const float4*)&Bsrc[(size_t)lm * 256 + k0 + lc*4];
        Bs[lc*4+0][lm] = b4.x; Bs[lc*4+1][lm] = b4.y;
        Bs[lc*4+2][lm] = b4.z; Bs[lc*4+3][lm] = b4.w;
        __syncthreads();
        #pragma unroll
        for (int kk = 0; kk < 16; kk++) {
            ull a0 = *(const ull*)&As[kk][ty*4];
            ull a1 = *(const ull*)&As[kk][ty*4+2];
            float4 bf = *(const float4*)&Bs[kk][tx*4];
            ull b0 = f2pack(bf.x, bf.x), b1 = f2pack(bf.y, bf.y);
            ull b2 = f2pack(bf.z, bf.z), b3 = f2pack(bf.w, bf.w);
            acc[0][0] = f2fma(b0, a0, acc[0][0]); acc[0][1] = f2fma(b0, a1, acc[0][1]);
            acc[1][0] = f2fma(b1, a0, acc[1][0]); acc[1][1] = f2fma(b1, a1, acc[1][1]);
            acc[2][0] = f2fma(b2, a0, acc[2][0]); acc[2][1] = f2fma(b2, a1, acc[2][1]);
            acc[3][0] = f2fma(b3, a0, acc[3][0]); acc[3][1] = f2fma(b3, a1, acc[3][1]);
        }
        __syncthreads();
    }

    float v[4][4];
    #pragma unroll
    for (int n = 0; n < 4; n++) {
        f2unpack(acc[n][0], v[n][0], v[n][1]);
        f2unpack(acc[n][1], v[n][2], v[n][3]);
    }
    const int c = bn + tx*4;
    #pragma unroll
    for (int r = 0; r < 4; r++) {
        int row = bm + ty*4 + r;
        float4 o = make_float4(v[0][r], v[1][r], v[2][r], v[3][r]);
        int b = row >> 9, s = row & 511;
        if (c < 256) {
            int h = c >> 5, a = c & 31;
            *(float4*)&g_qh[((size_t)((b*8+h)*512 + s))*32 + a] = o;
        } else if (c < 512) {
            int kc = c - 256, h = kc >> 5, a = kc & 31;
            *(float4*)&g_kh[((size_t)((b*8+h)*512 + s))*32 + a] = o;
        } else {
            *(float4*)&g_v[(size_t)row * 256 + (c - 512)] = o;
        }
    }
}

// =========================================================================
// Kernel 2: v min/max per (b,d) + p/invp.  grid (8 dchunk, 2 b), 256 thr.
// =========================================================================
__global__ __launch_bounds__(256) void vstats_kernel(const float* __restrict__ p_param) {
    __shared__ float smn[8][32], smx[8][32];
    const int b = blockIdx.y, dc = blockIdx.x;
    const int dd = threadIdx.x & 31, sl = threadIdx.x >> 5;
    const int d = dc*32 + dd;
    float mn = 1e30f, mx = -1e30f;
    const float* base = g_v + (size_t)(b*512 + sl*64) * 256 + d;
    #pragma unroll 4
    for (int i = 0; i < 64; i++) {
        float v = base[(size_t)i * 256];
        mn = fminf(mn, v); mx = fmaxf(mx, v);
    }
    smn[sl][dd] = mn; smx[sl][dd] = mx;
    __syncthreads();
    if (sl == 0) {
        #pragma unroll
        for (int t = 1; t < 8; t++) {
            mn = fminf(mn, smn[t][dd]); mx = fmaxf(mx, smx[t][dd]);
        }
        float range = mx - mn + EPSF;
        g_vmin   [b*256 + d] = mn;
        g_nscale [b*256 + d] = (1.0f - B_CONSTF) / range;
        g_unscale[b*256 + d] = range / (1.0f - B_CONSTF);
        if (b == 0) {
            float pp = p_param[d];
            float p  = 50000.0f * tanhf(0.005f * pp) + 1.0f;
            if (p == 0.0f) p = 1e-4f;
            g_p[d] = p; g_invp[d] = 1.0f / p;
        }
    }
}

// =========================================================================
// Kernel 3: vz = v_norm^p per-head.  grid (8 schunk, 16 bh), 256 thr.
// =========================================================================
__global__ __launch_bounds__(256) void vz_kernel() {
    __shared__ float s_p[32], s_ns[32], s_vm[32];
    const int bh = blockIdx.y, sc = blockIdx.x;
    const int b = bh >> 3, h = bh & 7;
    const int tid = threadIdx.x;
    if (tid < 32) {
        int d = h*32 + tid;
        s_p[tid]  = g_p[d];
        s_ns[tid] = g_nscale[b*256 + d];
        s_vm[tid] = g_vmin[b*256 + d];
    }
    __syncthreads();
    const int a = tid & 31, sq = tid >> 5;
    #pragma unroll
    for (int it = 0; it < 8; it++) {
        int s = sc*64 + it*8 + sq;
        float v  = g_v[(size_t)(b*512 + s) * 256 + h*32 + a];
        float vn = (v - s_vm[a]) * s_ns[a] + B_CONSTF;
        g_vz[((size_t)(bh*512 + s))*32 + a] = __expf(s_p[a] * __logf(vn));
    }
}

// =========================================================================
// Kernel 4: pass1 scores.  S[bh] = exp(Q@K^T * scale) + row-sum partials.
// grid (8 kt, 4 qt, 16 bh) = 512 blocks, 256 thr.
// Tile 128q x 64k, K=32 staged ONCE (no k-loop). Micro 8m x 4n per thread.
// =========================================================================
__global__ __launch_bounds__(256) void pass1_kernel() {
    __shared__ float As[32][132];   // [kk][m] 128 rows + pad4 (528B rows, 16B-mult)
    __shared__ float Bs[32][68];    // [kk][n] 64 cols  + pad4 (272B rows, 16B-mult)
    const int kt = blockIdx.x, qt = blockIdx.y, bh = blockIdx.z;
    const int tid = threadIdx.x, tx = tid & 15, ty = tid >> 4;  // ty 0..15
    const float* Aq = g_qh + (size_t)bh*512*32 + (size_t)qt*128*32;
    const float* Bk = g_kh + (size_t)bh*512*32 + (size_t)kt*64*32;

    // fill A: 128x32, 16 floats/thread
    {
        const int lm = tid & 127, lh = tid >> 7;   // row, col-half
        #pragma unroll
        for (int r = 0; r < 2; r++) {
            int c = lh*16 + r*8;
            float4 x0 = *(const float4*)&Aq[lm*32 + c];
            float4 x1 = *(const float4*)&Aq[lm*32 + c + 4];
            As[c+0][lm] = x0.x; As[c+1][lm] = x0.y; As[c+2][lm] = x0.z; As[c+3][lm] = x0.w;
            As[c+4][lm] = x1.x; As[c+5][lm] = x1.y; As[c+6][lm] = x1.z; As[c+7][lm] = x1.w;
        }
    }
    // fill B: 64x32, 8 floats/thread
    {
        const int ln = tid & 63, lk = tid >> 6;    // row, col-group
        #pragma unroll
        for (int r = 0; r < 2; r++) {
            int c = lk*8 + r*4;
            float4 x = *(const float4*)&Bk[ln*32 + c];
            Bs[c+0][ln] = x.x; Bs[c+1][ln] = x.y; Bs[c+2][ln] = x.z; Bs[c+3][ln] = x.w;
        }
    }
    __syncthreads();

    ull acc[4][4];
    #pragma unroll
    for (int n = 0; n < 4; n++)
        #pragma unroll
        for (int i = 0; i < 4; i++) acc[n][i] = 0ULL;

    #pragma unroll
    for (int kk = 0; kk < 32; kk++) {
        ulonglong2 A0 = *(const ulonglong2*)&As[kk][ty*8];
        ulonglong2 A1 = *(const ulonglong2*)&As[kk][ty*8 + 4];
        ull a0 = A0.x, a1 = A0.y, a2 = A1.x, a3 = A1.y;
        float4 bf = *(const float4*)&Bs[kk][tx*4];
        ull b0 = f2pack(bf.x, bf.x), b1 = f2pack(bf.y, bf.y);
        ull b2 = f2pack(bf.z, bf.z), b3 = f2pack(bf.w, bf.w);
        acc[0][0]=f2fma(b0,a0,acc[0][0]); acc[0][1]=f2fma(b0,a1,acc[0][1]);
        acc[0][2]=f2fma(b0,a2,acc[0][2]); acc[0][3]=f2fma(b0,a3,acc[0][3]);
        acc[1][0]=f2fma(b1,a0,acc[1][0]); acc[1][1]=f2fma(b1,a1,acc[1][1]);
        acc[1][2]=f2fma(b1,a2,acc[1][2]); acc[1][3]=f2fma(b1,a3,acc[1][3]);
        acc[2][0]=f2fma(b2,a0,acc[2][0]); acc[2][1]=f2fma(b2,a1,acc[2][1]);
        acc[2][2]=f2fma(b2,a2,acc[2][2]); acc[2][3]=f2fma(b2,a3,acc[2][3]);
        acc[3][0]=f2fma(b3,a0,acc[3][0]); acc[3][1]=f2fma(b3,a1,acc[3][1]);
        acc[3][2]=f2fma(b3,a2,acc[3][2]); acc[3][3]=f2fma(b3,a3,acc[3][3]);
    }

    float w[4][8];
    #pragma unroll
    for (int n = 0; n < 4; n++)
        #pragma unroll
        for (int i = 0; i < 4; i++)
            f2unpack(acc[n][i], w[n][2*i], w[n][2*i+1]);

    float rs[8];
    #pragma unroll
    for (int r = 0; r < 8; r++) rs[r] = 0.f;
    #pragma unroll
    for (int n = 0; n < 4; n++)
        #pragma unroll
        for (int r = 0; r < 8; r++) {
            w[n][r] = __expf(w[n][r] * SCALEF);
            rs[r] += w[n][r];
        }
    float* Sout = g_s + (size_t)bh*512*512;
    #pragma unroll
    for (int r = 0; r < 8; r++) {
        int row = qt*128 + ty*8 + r;
        float4 o = make_float4(w[0][r], w[1][r], w[2][r], w[3][r]);
        *(float4*)&Sout[(size_t)row*512 + kt*64 + tx*4] = o;
    }
    // reduce rowsum over 16 tx lanes (same ty within half-warp)
    #pragma unroll
    for (int r = 0; r < 8; r++) {
        rs[r] += __shfl_xor_sync(0xffffffffu, rs[r], 1);
        rs[r] += __shfl_xor_sync(0xffffffffu, rs[r], 2);
        rs[r] += __shfl_xor_sync(0xffffffffu, rs[r], 4);
        rs[r] += __shfl_xor_sync(0xffffffffu, rs[r], 8);
    }
    if (tx == 0) {
        #pragma unroll
        for (int r = 0; r < 8; r++)
            g_lp[((size_t)(bh*8 + kt))*512 + qt*128 + ty*8 + r] = rs[r];
    }
}

// =========================================================================
// Kernel 5: pass2 + fused power-mean epilogue.  Full K=512.
// grid (8 mt, 16 bh) = 128 blocks, 256 thr.
// Tile 64m x 32n, BK=32, micro 4m x 2n per thread.
// A fill: 256 thr x 8 floats = 64 rows x 32 cols.  c = lh*8 + r*4 (lh 0..3).
// =========================================================================
__global__ __launch_bounds__(256) void pass2_kernel() {
    __shared__ float As[32][68];
    __shared__ float Bs[32][36];
    __shared__ float sinvL[64];
    const int mt = blockIdx.x, bh = blockIdx.y;
    const int b = bh >> 3, h = bh & 7;
    const int tid = threadIdx.x, tx = tid & 15, ty = tid >> 4;  // ty 0..15
    const float* Ab = g_s  + (size_t)bh*512*512 + (size_t)mt*64*512;
    const float* Bb = g_vz + (size_t)bh*512*32;
    const int lm = tid & 63, lh = tid >> 6;        // A fill: row lm, col-octet lh
    const int bkr = tid >> 3, bcl = (tid & 7) * 4; // B fill

    if (tid < 64) {
        int q = mt*64 + tid;
        float L = 0.f;
        #pragma unroll
        for (int kt = 0; kt < 8; kt++) L += g_lp[((size_t)(bh*8 + kt))*512 + q];
        sinvL[tid] = 1.0f / L;
    }

    ull acc[2][2];
    acc[0][0] = acc[0][1] = acc[1][0] = acc[1][1] = 0ULL;

    for (int k0 = 0; k0 < 512; k0 += 32) {
        #pragma unroll
        for (int r = 0; r < 2; r++) {
            int c = lh*8 + r*4;                       // lh 0..3 -> cols 0..31
            float4 a4 = *(const float4*)&Ab[(size_t)lm*512 + k0 + c];
            As[c+0][lm] = a4.x; As[c+1][lm] = a4.y;
            As[c+2][lm] = a4.z; As[c+3][lm] = a4.w;
        }
        float4 b4 = *(const float4*)&Bb[(size_t)(k0 + bkr)*32 + bcl];
        *(float4*)&Bs[bkr][bcl] = b4;
        __syncthreads();
        #pragma unroll
        for (int kk = 0; kk < 32; kk++) {
            ull a0 = *(const ull*)&As[kk][ty*4];
            ull a1 = *(const ull*)&As[kk][ty*4 + 2];
            float2 bf = *(const float2*)&Bs[kk][tx*2];
            ull b0 = f2pack(bf.x, bf.x), b1 = f2pack(bf.y, bf.y);
            acc[0][0] = f2fma(b0, a0, acc[0][0]); acc[0][1] = f2fma(b0, a1, acc[0][1]);
            acc[1][0] = f2fma(b1, a0, acc[1][0]); acc[1][1] = f2fma(b1, a1, acc[1][1]);
        }
        __syncthreads();
    }

    float v[2][4];
    f2unpack(acc[0][0], v[0][0], v[0][1]); f2unpack(acc[0][1], v[0][2], v[0][3]);
    f2unpack(acc[1][0], v[1][0], v[1][1]); f2unpack(acc[1][1], v[1][2], v[1][3]);

    const int a0 = h*32 + tx*2;
    const float ip0 = g_invp[a0],            ip1 = g_invp[a0+1];
    const float us0 = g_unscale[b*256 + a0], us1 = g_unscale[b*256 + a0 + 1];
    const float vm0 = g_vmin[b*256 + a0],    vm1 = g_vmin[b*256 + a0 + 1];
    #pragma unroll
    for (int r = 0; r < 4; r++) {
        int q = mt*64 + ty*4 + r;
        float il = sinvL[ty*4 + r];
        float e0 = __expf(__logf(v[0][r] * il) * ip0);
        float e1 = __expf(__logf(v[1][r] * il) * ip1);
        float2 o = make_float2((e0 - B_CONSTF) * us0 + vm0,
                               (e1 - B_CONSTF) * us1 + vm1);
        *(float2*)&g_e[(size_t)(b*512 + q)*256 + a0] = o;
    }
}

// =========================================================================
// Kernel 6: output projection (round-4 proven form).
// out[1024][256] = g_e @ W_out^T.  grid (8, 16), 256 thr, micro 4m x 2n.
// =========================================================================
__global__ __launch_bounds__(256) void out_gemm(const float* __restrict__ Wo,
                                                float* __restrict__ out) {
    __shared__ float As[16][68];
    __shared__ float Bs[16][36];
    const int bn = blockIdx.x * 32;
    const int bm = blockIdx.y * 64;
    const int tid = threadIdx.x, tx = tid & 15, ty = tid >> 4;
    const int lm = tid >> 2, lc = tid & 3;
    const int ln = tid & 31, lk = tid >> 5;   // B fill (tid<128)

    ull acc[2][2];
    acc[0][0] = acc[0][1] = acc[1][0] = acc[1][1] = 0ULL;

    for (int k0 = 0; k0 < 256; k0 += 16) {
        float4 a4 = *(const float4*)&g_e[(size_t)(bm + lm)*256 + k0 + lc*4];
        As[lc*4+0][lm] = a4.x; As[lc*4+1][lm] = a4.y;
        As[lc*4+2][lm] = a4.z; As[lc*4+3][lm] = a4.w;
        if (tid < 128) {
            float4 w4 = *(const float4*)&Wo[(size_t)(bn + ln)*256 + k0 + lk*4];
            Bs[lk*4+0][ln] = w4.x; Bs[lk*4+1][ln] = w4.y;
            Bs[lk*4+2][ln] = w4.z; Bs[lk*4+3][ln] = w4.w;
        }
        __syncthreads();
        #pragma unroll
        for (int kk = 0; kk < 16; kk++) {
            ull a0 = *(const ull*)&As[kk][ty*4];
            ull a1 = *(const ull*)&As[kk][ty*4+2];
            float2 bf = *(const float2*)&Bs[kk][tx*2];
            ull b0 = f2pack(bf.x, bf.x), b1 = f2pack(bf.y, bf.y);
            acc[0][0] = f2fma(b0, a0, acc[0][0]); acc[0][1] = f2fma(b0, a1, acc[0][1]);
            acc[1][0] = f2fma(b1, a0, acc[1][0]); acc[1][1] = f2fma(b1, a1, acc[1][1]);
        }
        __syncthreads();
    }
    float v[2][4];
    f2unpack(acc[0][0], v[0][0], v[0][1]); f2unpack(acc[0][1], v[0][2], v[0][3]);
    f2unpack(acc[1][0], v[1][0], v[1][1]); f2unpack(acc[1][1], v[1][2], v[1][3]);
    #pragma unroll
    for (int r = 0; r < 4; r++) {
        float2 o = make_float2(v[0][r], v[1][r]);
        *(float2*)&out[(size_t)(bm + ty*4 + r)*256 + bn + tx*2] = o;
    }
}

// ---------------- launch ----------------
extern "C" void kernel_launch(void* const* d_in, const int* in_sizes, int n_in,
                              void* d_out, int out_size) {
    const float* context = (const float*)d_in[0];
    const float* W_Q     = (const float*)d_in[1];
    const float* W_KV    = (const float*)d_in[2];
    const float* W_out   = (const float*)d_in[3];
    const float* p_param = (const float*)d_in[4];
    float* out = (float*)d_out;

    qkv_gemm    <<<dim3(12, 16),    256>>>(context, W_Q, W_KV);
    vstats_kernel<<<dim3(8, 2),     256>>>(p_param);
    vz_kernel   <<<dim3(8, 16),     256>>>();
    pass1_kernel<<<dim3(8, 4, 16),  256>>>();
    pass2_kernel<<<dim3(8, 16),     256>>>();
    out_gemm    <<<dim3(8, 16),     256>>>(W_out, out);
}

// round 8
// speedup vs baseline: 1.1924x; 1.0902x over previous
#include <cuda_runtime.h>
#include <math.h>

#define B_CONSTF 0.9f
#define EPSF 1e-10f
#define SCALEF 0.0625f

typedef unsigned long long ull;

// ---------------- device scratch ----------------
__device__ float g_qh[16*512*32];    // per-head Q   [bh][s][32]
__device__ float g_kh[16*512*32];    // per-head K   [bh][s][32]
__device__ float g_v [1024*256];     // V row-major  [b*s][256]
__device__ float g_vz[16*512*32];    // v_norm^p     [bh][s][32]
__device__ float g_s [16*512*512];   // exp scores   [bh][q][k]  (16.8MB)
__device__ float g_lp[16*8*512];     // row-sum partials [bh][ktile][q]
__device__ float g_e [1024*256];     // power-mean result (row-major)
__device__ float g_vmin[512], g_nscale[512], g_unscale[512];
__device__ float g_p[256], g_invp[256];

// ---------------- f32x2 helpers ----------------
__device__ __forceinline__ ull f2pack(float lo, float hi) {
    ull r; asm("mov.b64 %0, {%1, %2};" : "=l"(r) : "f"(lo), "f"(hi)); return r;
}
__device__ __forceinline__ void f2unpack(ull v, float& lo, float& hi) {
    asm("mov.b64 {%0, %1}, %2;" : "=f"(lo), "=f"(hi) : "l"(v));
}
__device__ __forceinline__ ull f2fma(ull a, ull b, ull c) {
    ull d; asm("fma.rn.f32x2 %0, %1, %2, %3;" : "=l"(d) : "l"(a), "l"(b), "l"(c)); return d;
}

// =========================================================================
// Kernel 1: fused QKV projection, register-prefetch double buffered.
// C[1024][768] = ctx @ [W_Q; W_KV]^T.  64x64 tiles, 256 thr, micro 4m x 4n.
// =========================================================================
__global__ __launch_bounds__(256) void qkv_gemm(
    const float* __restrict__ ctx, const float* __restrict__ W_Q,
    const float* __restrict__ W_KV)
{
    __shared__ float As[16][68];
    __shared__ float Bs[16][68];
    const int tid = threadIdx.x;
    const int tx = tid & 15, ty = tid >> 4;
    const int bm = blockIdx.y * 64;
    const int bn = blockIdx.x * 64;
    const float* Bsrc = (bn < 256) ? (W_Q + (size_t)bn * 256)
                                   : (W_KV + (size_t)(bn - 256) * 256);
    const int lm = tid >> 2, lc = tid & 3;

    ull acc[4][2];
    #pragma unroll
    for (int n = 0; n < 4; n++) { acc[n][0] = 0ULL; acc[n][1] = 0ULL; }

    float4 pa = *(const float4*)&ctx [(size_t)(bm + lm) * 256 + lc*4];
    float4 pb = *(const float4*)&Bsrc[(size_t)lm * 256 + lc*4];

    for (int k0 = 0; k0 < 256; k0 += 16) {
        As[lc*4+0][lm] = pa.x; As[lc*4+1][lm] = pa.y;
        As[lc*4+2][lm] = pa.z; As[lc*4+3][lm] = pa.w;
        Bs[lc*4+0][lm] = pb.x; Bs[lc*4+1][lm] = pb.y;
        Bs[lc*4+2][lm] = pb.z; Bs[lc*4+3][lm] = pb.w;
        __syncthreads();
        if (k0 + 16 < 256) {
            pa = *(const float4*)&ctx [(size_t)(bm + lm) * 256 + k0 + 16 + lc*4];
            pb = *(const float4*)&Bsrc[(size_t)lm * 256 + k0 + 16 + lc*4];
        }
        #pragma unroll
        for (int kk = 0; kk < 16; kk++) {
            ull a0 = *(const ull*)&As[kk][ty*4];
            ull a1 = *(const ull*)&As[kk][ty*4+2];
            float4 bf = *(const float4*)&Bs[kk][tx*4];
            ull b0 = f2pack(bf.x, bf.x), b1 = f2pack(bf.y, bf.y);
            ull b2 = f2pack(bf.z, bf.z), b3 = f2pack(bf.w, bf.w);
            acc[0][0] = f2fma(b0, a0, acc[0][0]); acc[0][1] = f2fma(b0, a1, acc[0][1]);
            acc[1][0] = f2fma(b1, a0, acc[1][0]); acc[1][1] = f2fma(b1, a1, acc[1][1]);
            acc[2][0] = f2fma(b2, a0, acc[2][0]); acc[2][1] = f2fma(b2, a1, acc[2][1]);
            acc[3][0] = f2fma(b3, a0, acc[3][0]); acc[3][1] = f2fma(b3, a1, acc[3][1]);
        }
        __syncthreads();
    }

    float v[4][4];
    #pragma unroll
    for (int n = 0; n < 4; n++) {
        f2unpack(acc[n][0], v[n][0], v[n][1]);
        f2unpack(acc[n][1], v[n][2], v[n][3]);
    }
    const int c = bn + tx*4;
    #pragma unroll
    for (int r = 0; r < 4; r++) {
        int row = bm + ty*4 + r;
        float4 o = make_float4(v[0][r], v[1][r], v[2][r], v[3][r]);
        int b = row >> 9, s = row & 511;
        if (c < 256) {
            int h = c >> 5, a = c & 31;
            *(float4*)&g_qh[((size_t)((b*8+h)*512 + s))*32 + a] = o;
        } else if (c < 512) {
            int kc = c - 256, h = kc >> 5, a = kc & 31;
            *(float4*)&g_kh[((size_t)((b*8+h)*512 + s))*32 + a] = o;
        } else {
            *(float4*)&g_v[(size_t)row * 256 + (c - 512)] = o;
        }
    }
}

// =========================================================================
// Kernel 2: v min/max per (b,d) + p/invp.  grid (8 dchunk, 2 b), 256 thr.
// =========================================================================
__global__ __launch_bounds__(256) void vstats_kernel(const float* __restrict__ p_param) {
    __shared__ float smn[8][32], smx[8][32];
    const int b = blockIdx.y, dc = blockIdx.x;
    const int dd = threadIdx.x & 31, sl = threadIdx.x >> 5;
    const int d = dc*32 + dd;
    float mn = 1e30f, mx = -1e30f;
    const float* base = g_v + (size_t)(b*512 + sl*64) * 256 + d;
    #pragma unroll 4
    for (int i = 0; i < 64; i++) {
        float v = base[(size_t)i * 256];
        mn = fminf(mn, v); mx = fmaxf(mx, v);
    }
    smn[sl][dd] = mn; smx[sl][dd] = mx;
    __syncthreads();
    if (sl == 0) {
        #pragma unroll
        for (int t = 1; t < 8; t++) {
            mn = fminf(mn, smn[t][dd]); mx = fmaxf(mx, smx[t][dd]);
        }
        float range = mx - mn + EPSF;
        g_vmin   [b*256 + d] = mn;
        g_nscale [b*256 + d] = (1.0f - B_CONSTF) / range;
        g_unscale[b*256 + d] = range / (1.0f - B_CONSTF);
        if (b == 0) {
            float pp = p_param[d];
            float p  = 50000.0f * tanhf(0.005f * pp) + 1.0f;
            if (p == 0.0f) p = 1e-4f;
            g_p[d] = p; g_invp[d] = 1.0f / p;
        }
    }
}

// =========================================================================
// Kernel 3: vz = v_norm^p per-head.  grid (8 schunk, 16 bh), 256 thr.
// =========================================================================
__global__ __launch_bounds__(256) void vz_kernel() {
    __shared__ float s_p[32], s_ns[32], s_vm[32];
    const int bh = blockIdx.y, sc = blockIdx.x;
    const int b = bh >> 3, h = bh & 7;
    const int tid = threadIdx.x;
    if (tid < 32) {
        int d = h*32 + tid;
        s_p[tid]  = g_p[d];
        s_ns[tid] = g_nscale[b*256 + d];
        s_vm[tid] = g_vmin[b*256 + d];
    }
    __syncthreads();
    const int a = tid & 31, sq = tid >> 5;
    #pragma unroll
    for (int it = 0; it < 8; it++) {
        int s = sc*64 + it*8 + sq;
        float v  = g_v[(size_t)(b*512 + s) * 256 + h*32 + a];
        float vn = (v - s_vm[a]) * s_ns[a] + B_CONSTF;
        g_vz[((size_t)(bh*512 + s))*32 + a] = __expf(s_p[a] * __logf(vn));
    }
}

// =========================================================================
// Kernel 4: pass1 scores, SINGLE WAVE.  grid (8 kt, 16 bh) = 128 blocks.
// Each block stages its K tile (64x32) ONCE and loops qt=0..3 over Q tiles
// (128x32 each), register-prefetching the next Q tile during compute.
// Micro 8m x 4n per thread, 256 thr.
// =========================================================================
__global__ __launch_bounds__(256) void pass1_kernel() {
    __shared__ float As[32][132];   // [kk][m] 128 rows + pad4
    __shared__ float Bs[32][68];    // [kk][n] 64 cols  + pad4
    const int kt = blockIdx.x, bh = blockIdx.y;
    const int tid = threadIdx.x, tx = tid & 15, ty = tid >> 4;  // ty 0..15
    const float* Bk   = g_kh + (size_t)bh*512*32 + (size_t)kt*64*32;
    const float* Qbase= g_qh + (size_t)bh*512*32;
    float* Sout = g_s + (size_t)bh*512*512;

    // fill B once: 64x32, 8 floats/thread
    {
        const int ln = tid & 63, lk = tid >> 6;
        #pragma unroll
        for (int r = 0; r < 2; r++) {
            int c = lk*8 + r*4;
            float4 x = *(const float4*)&Bk[ln*32 + c];
            Bs[c+0][ln] = x.x; Bs[c+1][ln] = x.y; Bs[c+2][ln] = x.z; Bs[c+3][ln] = x.w;
        }
    }

    const int lm = tid & 127, lh = tid >> 7;   // A fill: row, col-half
    // prefetch Q tile for qt=0: 16 floats/thread
    float4 pA[4];
    #pragma unroll
    for (int r = 0; r < 2; r++) {
        int c = lh*16 + r*8;
        pA[2*r]   = *(const float4*)&Qbase[lm*32 + c];
        pA[2*r+1] = *(const float4*)&Qbase[lm*32 + c + 4];
    }

    for (int qt = 0; qt < 4; qt++) {
        // store prefetched A tile
        #pragma unroll
        for (int r = 0; r < 2; r++) {
            int c = lh*16 + r*8;
            float4 x0 = pA[2*r], x1 = pA[2*r+1];
            As[c+0][lm] = x0.x; As[c+1][lm] = x0.y; As[c+2][lm] = x0.z; As[c+3][lm] = x0.w;
            As[c+4][lm] = x1.x; As[c+5][lm] = x1.y; As[c+6][lm] = x1.z; As[c+7][lm] = x1.w;
        }
        __syncthreads();
        // prefetch next Q tile
        if (qt < 3) {
            const float* Aq = Qbase + (size_t)(qt+1)*128*32;
            #pragma unroll
            for (int r = 0; r < 2; r++) {
                int c = lh*16 + r*8;
                pA[2*r]   = *(const float4*)&Aq[lm*32 + c];
                pA[2*r+1] = *(const float4*)&Aq[lm*32 + c + 4];
            }
        }

        ull acc[4][4];
        #pragma unroll
        for (int n = 0; n < 4; n++)
            #pragma unroll
            for (int i = 0; i < 4; i++) acc[n][i] = 0ULL;

        #pragma unroll
        for (int kk = 0; kk < 32; kk++) {
            ulonglong2 A0 = *(const ulonglong2*)&As[kk][ty*8];
            ulonglong2 A1 = *(const ulonglong2*)&As[kk][ty*8 + 4];
            ull a0 = A0.x, a1 = A0.y, a2 = A1.x, a3 = A1.y;
            float4 bf = *(const float4*)&Bs[kk][tx*4];
            ull b0 = f2pack(bf.x, bf.x), b1 = f2pack(bf.y, bf.y);
            ull b2 = f2pack(bf.z, bf.z), b3 = f2pack(bf.w, bf.w);
            acc[0][0]=f2fma(b0,a0,acc[0][0]); acc[0][1]=f2fma(b0,a1,acc[0][1]);
            acc[0][2]=f2fma(b0,a2,acc[0][2]); acc[0][3]=f2fma(b0,a3,acc[0][3]);
            acc[1][0]=f2fma(b1,a0,acc[1][0]); acc[1][1]=f2fma(b1,a1,acc[1][1]);
            acc[1][2]=f2fma(b1,a2,acc[1][2]); acc[1][3]=f2fma(b1,a3,acc[1][3]);
            acc[2][0]=f2fma(b2,a0,acc[2][0]); acc[2][1]=f2fma(b2,a1,acc[2][1]);
            acc[2][2]=f2fma(b2,a2,acc[2][2]); acc[2][3]=f2fma(b2,a3,acc[2][3]);
            acc[3][0]=f2fma(b3,a0,acc[3][0]); acc[3][1]=f2fma(b3,a1,acc[3][1]);
            acc[3][2]=f2fma(b3,a2,acc[3][2]); acc[3][3]=f2fma(b3,a3,acc[3][3]);
        }

        float w[4][8];
        #pragma unroll
        for (int n = 0; n < 4; n++)
            #pragma unroll
            for (int i = 0; i < 4; i++)
                f2unpack(acc[n][i], w[n][2*i], w[n][2*i+1]);

        float rs[8];
        #pragma unroll
        for (int r = 0; r < 8; r++) rs[r] = 0.f;
        #pragma unroll
        for (int n = 0; n < 4; n++)
            #pragma unroll
            for (int r = 0; r < 8; r++) {
                w[n][r] = __expf(w[n][r] * SCALEF);
                rs[r] += w[n][r];
            }
        #pragma unroll
        for (int r = 0; r < 8; r++) {
            int row = qt*128 + ty*8 + r;
            float4 o = make_float4(w[0][r], w[1][r], w[2][r], w[3][r]);
            *(float4*)&Sout[(size_t)row*512 + kt*64 + tx*4] = o;
        }
        #pragma unroll
        for (int r = 0; r < 8; r++) {
            rs[r] += __shfl_xor_sync(0xffffffffu, rs[r], 1);
            rs[r] += __shfl_xor_sync(0xffffffffu, rs[r], 2);
            rs[r] += __shfl_xor_sync(0xffffffffu, rs[r], 4);
            rs[r] += __shfl_xor_sync(0xffffffffu, rs[r], 8);
        }
        if (tx == 0) {
            #pragma unroll
            for (int r = 0; r < 8; r++)
                g_lp[((size_t)(bh*8 + kt))*512 + qt*128 + ty*8 + r] = rs[r];
        }
        __syncthreads();   // As consumed; safe to refill next qt
    }
}

// =========================================================================
// Kernel 5: pass2 + fused power-mean epilogue, register-prefetch buffered.
// Full K=512.  grid (8 mt, 16 bh) = 128 blocks, 256 thr.
// Tile 64m x 32n, BK=32, micro 4m x 2n per thread.
// =========================================================================
__global__ __launch_bounds__(256) void pass2_kernel() {
    __shared__ float As[32][68];
    __shared__ float Bs[32][36];
    __shared__ float sinvL[64];
    const int mt = blockIdx.x, bh = blockIdx.y;
    const int b = bh >> 3, h = bh & 7;
    const int tid = threadIdx.x, tx = tid & 15, ty = tid >> 4;  // ty 0..15
    const float* Ab = g_s  + (size_t)bh*512*512 + (size_t)mt*64*512;
    const float* Bb = g_vz + (size_t)bh*512*32;
    const int lm = tid & 63, lh = tid >> 6;        // A fill: row, col-octet
    const int bkr = tid >> 3, bcl = (tid & 7) * 4; // B fill

    if (tid < 64) {
        int q = mt*64 + tid;
        float L = 0.f;
        #pragma unroll
        for (int kt = 0; kt < 8; kt++) L += g_lp[((size_t)(bh*8 + kt))*512 + q];
        sinvL[tid] = 1.0f / L;
    }

    ull acc[2][2];
    acc[0][0] = acc[0][1] = acc[1][0] = acc[1][1] = 0ULL;

    float4 pa0 = *(const float4*)&Ab[(size_t)lm*512 + lh*8];
    float4 pa1 = *(const float4*)&Ab[(size_t)lm*512 + lh*8 + 4];
    float4 pb  = *(const float4*)&Bb[(size_t)bkr*32 + bcl];

    for (int k0 = 0; k0 < 512; k0 += 32) {
        {
            int c = lh*8;
            As[c+0][lm] = pa0.x; As[c+1][lm] = pa0.y;
            As[c+2][lm] = pa0.z; As[c+3][lm] = pa0.w;
            As[c+4][lm] = pa1.x; As[c+5][lm] = pa1.y;
            As[c+6][lm] = pa1.z; As[c+7][lm] = pa1.w;
        }
        *(float4*)&Bs[bkr][bcl] = pb;
        __syncthreads();
        if (k0 + 32 < 512) {
            pa0 = *(const float4*)&Ab[(size_t)lm*512 + k0 + 32 + lh*8];
            pa1 = *(const float4*)&Ab[(size_t)lm*512 + k0 + 32 + lh*8 + 4];
            pb  = *(const float4*)&Bb[(size_t)(k0 + 32 + bkr)*32 + bcl];
        }
        #pragma unroll
        for (int kk = 0; kk < 32; kk++) {
            ull a0 = *(const ull*)&As[kk][ty*4];
            ull a1 = *(const ull*)&As[kk][ty*4 + 2];
            float2 bf = *(const float2*)&Bs[kk][tx*2];
            ull b0 = f2pack(bf.x, bf.x), b1 = f2pack(bf.y, bf.y);
            acc[0][0] = f2fma(b0, a0, acc[0][0]); acc[0][1] = f2fma(b0, a1, acc[0][1]);
            acc[1][0] = f2fma(b1, a0, acc[1][0]); acc[1][1] = f2fma(b1, a1, acc[1][1]);
        }
        __syncthreads();
    }

    float v[2][4];
    f2unpack(acc[0][0], v[0][0], v[0][1]); f2unpack(acc[0][1], v[0][2], v[0][3]);
    f2unpack(acc[1][0], v[1][0], v[1][1]); f2unpack(acc[1][1], v[1][2], v[1][3]);

    const int a0 = h*32 + tx*2;
    const float ip0 = g_invp[a0],            ip1 = g_invp[a0+1];
    const float us0 = g_unscale[b*256 + a0], us1 = g_unscale[b*256 + a0 + 1];
    const float vm0 = g_vmin[b*256 + a0],    vm1 = g_vmin[b*256 + a0 + 1];
    #pragma unroll
    for (int r = 0; r < 4; r++) {
        int q = mt*64 + ty*4 + r;
        float il = sinvL[ty*4 + r];
        float e0 = __expf(__logf(v[0][r] * il) * ip0);
        float e1 = __expf(__logf(v[1][r] * il) * ip1);
        float2 o = make_float2((e0 - B_CONSTF) * us0 + vm0,
                               (e1 - B_CONSTF) * us1 + vm1);
        *(float2*)&g_e[(size_t)(b*512 + q)*256 + a0] = o;
    }
}

// =========================================================================
// Kernel 6: output projection, register-prefetch buffered.
// out[1024][256] = g_e @ W_out^T.  grid (8, 16), 256 thr, micro 4m x 2n.
// =========================================================================
__global__ __launch_bounds__(256) void out_gemm(const float* __restrict__ Wo,
                                                float* __restrict__ out) {
    __shared__ float As[16][68];
    __shared__ float Bs[16][36];
    const int bn = blockIdx.x * 32;
    const int bm = blockIdx.y * 64;
    const int tid = threadIdx.x, tx = tid & 15, ty = tid >> 4;
    const int lm = tid >> 2, lc = tid & 3;
    const int ln = tid & 31, lk = tid >> 5;   // B fill (tid<128)

    ull acc[2][2];
    acc[0][0] = acc[0][1] = acc[1][0] = acc[1][1] = 0ULL;

    float4 pa = *(const float4*)&g_e[(size_t)(bm + lm)*256 + lc*4];
    float4 pb;
    if (tid < 128) pb = *(const float4*)&Wo[(size_t)(bn + ln)*256 + lk*4];

    for (int k0 = 0; k0 < 256; k0 += 16) {
        As[lc*4+0][lm] = pa.x; As[lc*4+1][lm] = pa.y;
        As[lc*4+2][lm] = pa.z; As[lc*4+3][lm] = pa.w;
        if (tid < 128) {
            Bs[lk*4+0][ln] = pb.x; Bs[lk*4+1][ln] = pb.y;
            Bs[lk*4+2][ln] = pb.z; Bs[lk*4+3][ln] = pb.w;
        }
        __syncthreads();
        if (k0 + 16 < 256) {
            pa = *(const float4*)&g_e[(size_t)(bm + lm)*256 + k0 + 16 + lc*4];
            if (tid < 128) pb = *(const float4*)&Wo[(size_t)(bn + ln)*256 + k0 + 16 + lk*4];
        }
        #pragma unroll
        for (int kk = 0; kk < 16; kk++) {
            ull a0 = *(const ull*)&As[kk][ty*4];
            ull a1 = *(const ull*)&As[kk][ty*4+2];
            float2 bf = *(const float2*)&Bs[kk][tx*2];
            ull b0 = f2pack(bf.x, bf.x), b1 = f2pack(bf.y, bf.y);
            acc[0][0] = f2fma(b0, a0, acc[0][0]); acc[0][1] = f2fma(b0, a1, acc[0][1]);
            acc[1][0] = f2fma(b1, a0, acc[1][0]); acc[1][1] = f2fma(b1, a1, acc[1][1]);
        }
        __syncthreads();
    }
    float v[2][4];
    f2unpack(acc[0][0], v[0][0], v[0][1]); f2unpack(acc[0][1], v[0][2], v[0][3]);
    f2unpack(acc[1][0], v[1][0], v[1][1]); f2unpack(acc[1][1], v[1][2], v[1][3]);
    #pragma unroll
    for (int r = 0; r < 4; r++) {
        float2 o = make_float2(v[0][r], v[1][r]);
        *(float2*)&out[(size_t)(bm + ty*4 + r)*256 + bn + tx*2] = o;
    }
}

// ---------------- launch ----------------
extern "C" void kernel_launch(void* const* d_in, const int* in_sizes, int n_in,
                              void* d_out, int out_size) {
    const float* context = (const float*)d_in[0];
    const float* W_Q     = (const float*)d_in[1];
    const float* W_KV    = (const float*)d_in[2];
    const float* W_out   = (const float*)d_in[3];
    const float* p_param = (const float*)d_in[4];
    float* out = (float*)d_out;

    qkv_gemm    <<<dim3(12, 16),    256>>>(context, W_Q, W_KV);
    vstats_kernel<<<dim3(8, 2),     256>>>(p_param);
    vz_kernel   <<<dim3(8, 16),     256>>>();
    pass1_kernel<<<dim3(8, 16),     256>>>();
    pass2_kernel<<<dim3(8, 16),     256>>>();
    out_gemm    <<<dim3(8, 16),     256>>>(W_out, out);
}